// round 10
// baseline (speedup 1.0000x reference)
#include <cuda_runtime.h>
#include <cuda_bf16.h>
#include <math.h>
#include <stdint.h>

#define BZ 32
#define HH 56
#define WW 56
#define DIM 256
#define HEADS 8
#define WS 7
#define SHIFT 3
#define NTOK 49
#define NWIN 64
#define HEAD_DIM 32
#define HIDDEN 1024
#define MTOT (BZ*HH*WW)    // 100352 rows

typedef __nv_bfloat16 bf16;

// ---------------- scratch ----------------------------------------------------
__device__ bf16  g_hwin[(size_t)MTOT * DIM];
__device__ bf16  g_qkv [(size_t)MTOT * 3 * DIM];
__device__ bf16  g_attn[(size_t)MTOT * DIM];
__device__ float g_x1  [(size_t)MTOT * DIM];
__device__ bf16  g_h2  [(size_t)MTOT * HIDDEN];
__device__ bf16  g_wqkv[3 * DIM * DIM];
__device__ bf16  g_wproj[DIM * DIM];
__device__ bf16  g_wfc1[HIDDEN * DIM];
__device__ bf16  g_wfc2[DIM * HIDDEN];
__device__ bf16  g_comb[64 * 8 * 64 * 64];

__device__ __forceinline__ int remap_row(int m) {
    int b    = m / (NWIN * NTOK);
    int rem  = m - b * (NWIN * NTOK);
    int wimg = rem / NTOK;
    int n    = rem - wimg * NTOK;
    int hh = (wimg >> 3) * WS + n / WS + SHIFT; if (hh >= HH) hh -= HH;
    int ww = (wimg & 7) * WS + n % WS + SHIFT;  if (ww >= WW) ww -= WW;
    return b * (HH * WW) + hh * WW + ww;
}

// ---------------- ptx helpers -------------------------------------------------
__device__ __forceinline__ uint32_t smem_u32(const void* p) {
    return (uint32_t)__cvta_generic_to_shared(p);
}
__device__ __forceinline__ void cp16(uint32_t dst, const void* src) {
    asm volatile("cp.async.cg.shared.global [%0], [%1], 16;\n" :: "r"(dst), "l"(src));
}
__device__ __forceinline__ void cp_commit() { asm volatile("cp.async.commit_group;\n"); }
template<int N> __device__ __forceinline__ void cp_wait() {
    asm volatile("cp.async.wait_group %0;\n" :: "n"(N));
}
__device__ __forceinline__ void ldsm4(uint32_t* r, uint32_t addr) {
    asm volatile("ldmatrix.sync.aligned.m8n8.x4.shared.b16 {%0,%1,%2,%3}, [%4];"
                 : "=r"(r[0]), "=r"(r[1]), "=r"(r[2]), "=r"(r[3]) : "r"(addr));
}
__device__ __forceinline__ void mma_bf16(float* d, const uint32_t* a, const uint32_t* b) {
    asm volatile(
        "mma.sync.aligned.m16n8k16.row.col.f32.bf16.bf16.f32 "
        "{%0,%1,%2,%3}, {%4,%5,%6,%7}, {%8,%9}, {%0,%1,%2,%3};\n"
        : "+f"(d[0]), "+f"(d[1]), "+f"(d[2]), "+f"(d[3])
        : "r"(a[0]), "r"(a[1]), "r"(a[2]), "r"(a[3]), "r"(b[0]), "r"(b[1]));
}
__device__ __forceinline__ uint32_t pack_bf16x2(float a, float b) {
    __nv_bfloat162 h;
    h.x = __float2bfloat16(a); h.y = __float2bfloat16(b);
    return *(uint32_t*)&h;
}

// ---------------- fp32 -> bf16 weight convert (fused, 4 segs) -----------------
__global__ void cvt4_kernel(const float* s0, bf16* d0, int n0,
                            const float* s1, bf16* d1, int n1,
                            const float* s2, bf16* d2, int n2,
                            const float* s3, bf16* d3, int n3) {
    const float* s; bf16* d; int n;
    switch (blockIdx.y) {
        case 0: s = s0; d = d0; n = n0; break;
        case 1: s = s1; d = d1; n = n1; break;
        case 2: s = s2; d = d2; n = n2; break;
        default: s = s3; d = d3; n = n3; break;
    }
    int i = (blockIdx.x * blockDim.x + threadIdx.x) * 4;
    if (i < n) {
        float4 v = *(const float4*)(s + i);
        __nv_bfloat162 p0 = {__float2bfloat16(v.x), __float2bfloat16(v.y)};
        __nv_bfloat162 p1 = {__float2bfloat16(v.z), __float2bfloat16(v.w)};
        *(__nv_bfloat162*)(d + i)     = p0;
        *(__nv_bfloat162*)(d + i + 2) = p1;
    }
}

// ---------------- comb bias precompute ---------------------------------------
__global__ void comb_kernel(const float* __restrict__ rpb,
                            const int* __restrict__ relix,
                            const float* __restrict__ mask,
                            bf16* __restrict__ comb) {
    int w = blockIdx.x, h = blockIdx.y;
    const float* mw = mask + w * (NTOK * NTOK);
    size_t base = ((size_t)(w * 8 + h)) << 12;
    for (int e = threadIdx.x; e < 4096; e += 256) {
        int n = e >> 6, m = e & 63;
        float v = -1e30f;
        if (n < NTOK && m < NTOK)
            v = rpb[relix[n * NTOK + m] * HEADS + h] + mw[n * NTOK + m];
        comb[base + e] = __float2bfloat16(v);
    }
}

// ---------------- LayerNorm (warp per row, bf16 out) -------------------------
template<bool SHIFTMAP>
__global__ void __launch_bounds__(256) ln_kernel(const float* __restrict__ x,
                                                 const float* __restrict__ gw,
                                                 const float* __restrict__ gb,
                                                 bf16* __restrict__ out) {
    int warp = threadIdx.x >> 5, lane = threadIdx.x & 31;
    int m = blockIdx.x * 8 + warp;
    const float* xr;
    if (SHIFTMAP) {
        int r = remap_row(m);
        xr = x + (size_t)r * DIM;
    } else {
        xr = x + (size_t)m * DIM;
    }
    float4 v0 = *(const float4*)(xr + lane * 4);
    float4 v1 = *(const float4*)(xr + 128 + lane * 4);
    float s  = v0.x + v0.y + v0.z + v0.w + v1.x + v1.y + v1.z + v1.w;
    float sq = v0.x*v0.x + v0.y*v0.y + v0.z*v0.z + v0.w*v0.w
             + v1.x*v1.x + v1.y*v1.y + v1.z*v1.z + v1.w*v1.w;
    #pragma unroll
    for (int o = 16; o; o >>= 1) {
        s  += __shfl_xor_sync(0xffffffffu, s,  o);
        sq += __shfl_xor_sync(0xffffffffu, sq, o);
    }
    float mu  = s * (1.0f / DIM);
    float var = sq * (1.0f / DIM) - mu * mu;
    float rs  = rsqrtf(var + 1e-5f);
    float4 w0 = *(const float4*)(gw + lane * 4);
    float4 w1 = *(const float4*)(gw + 128 + lane * 4);
    float4 b0 = *(const float4*)(gb + lane * 4);
    float4 b1 = *(const float4*)(gb + 128 + lane * 4);
    bf16* orow = out + (size_t)m * DIM;
    __nv_bfloat162 p;
    p = {__float2bfloat16((v0.x-mu)*rs*w0.x+b0.x), __float2bfloat16((v0.y-mu)*rs*w0.y+b0.y)};
    *(__nv_bfloat162*)(orow + lane*4)     = p;
    p = {__float2bfloat16((v0.z-mu)*rs*w0.z+b0.z), __float2bfloat16((v0.w-mu)*rs*w0.w+b0.w)};
    *(__nv_bfloat162*)(orow + lane*4 + 2) = p;
    p = {__float2bfloat16((v1.x-mu)*rs*w1.x+b1.x), __float2bfloat16((v1.y-mu)*rs*w1.y+b1.y)};
    *(__nv_bfloat162*)(orow + 128 + lane*4)     = p;
    p = {__float2bfloat16((v1.z-mu)*rs*w1.z+b1.z), __float2bfloat16((v1.w-mu)*rs*w1.w+b1.w)};
    *(__nv_bfloat162*)(orow + 128 + lane*4 + 2) = p;
}

// ---------------- bf16 mma.sync GEMM (NT), CTA 128x256, BK=64, 3-stage -------
// 512 threads, 16 warps in 4(m) x 4(n) grid; warp tile 32x64.
#define SROW 144                    // 128B data + 16B pad
#define ASTAGE (128 * SROW)         // 18432
#define BSTAGE (256 * SROW)         // 36864
#define STAGEB (ASTAGE + BSTAGE)    // 55296
#define NSTAGE 3
#define SMEM_DYN (NSTAGE * STAGEB)  // 165888
#define GTHREADS 512

template<int EPI>
__global__ void __launch_bounds__(GTHREADS, 1) bgemm(const bf16* __restrict__ A,
                                                    const bf16* __restrict__ Bm,
                                                    const float* __restrict__ bias,
                                                    void* __restrict__ Cv,
                                                    int M, int N, int K,
                                                    const float* __restrict__ res) {
    extern __shared__ __align__(16) char smem[];
    uint32_t sbase = smem_u32(smem);
    int tid = threadIdx.x;
    int bn = blockIdx.x, bm = blockIdx.y;
    int warp = tid >> 5, lane = tid & 31;
    int warpM = (warp & 3) * 32;
    int warpN = (warp >> 2) * 64;
    int r = lane >> 2, c = lane & 3;

    // fill coords: BK=64 -> A: 1024 16B-chunks (2/thr), B: 2048 (4/thr)
    int arw[2], acc_[2], brw[4], bcc[4];
    #pragma unroll
    for (int rpt = 0; rpt < 2; rpt++) {
        int ch = tid + rpt * GTHREADS;
        arw[rpt] = ch >> 3; acc_[rpt] = ch & 7;
    }
    #pragma unroll
    for (int rpt = 0; rpt < 4; rpt++) {
        int ch = tid + rpt * GTHREADS;
        brw[rpt] = ch >> 3; bcc[rpt] = ch & 7;
    }
    const bf16* Abase = A  + (size_t)(bm * 128) * K;
    const bf16* Bbase = Bm + (size_t)(bn * 256) * K;

    uint32_t aoff = (uint32_t)((lane & 15) * SROW + (lane >> 4) * 16);
    uint32_t boff = (uint32_t)(((lane & 7) + ((lane >> 4) << 3)) * SROW + ((lane & 8) ? 16 : 0));

    float acc[2][8][4];
    #pragma unroll
    for (int mi = 0; mi < 2; mi++)
        #pragma unroll
        for (int ni = 0; ni < 8; ni++)
            #pragma unroll
            for (int t = 0; t < 4; t++) acc[mi][ni][t] = 0.0f;

#define FILL(s, k0) do { \
    uint32_t ab = sbase + (s) * STAGEB; \
    uint32_t bb = ab + ASTAGE; \
    _Pragma("unroll") \
    for (int rpt = 0; rpt < 2; rpt++) \
        cp16(ab + arw[rpt] * SROW + acc_[rpt] * 16, \
             Abase + (size_t)arw[rpt] * K + (k0) + acc_[rpt] * 8); \
    _Pragma("unroll") \
    for (int rpt = 0; rpt < 4; rpt++) \
        cp16(bb + brw[rpt] * SROW + bcc[rpt] * 16, \
             Bbase + (size_t)brw[rpt] * K + (k0) + bcc[rpt] * 8); \
} while (0)

    int nk = K >> 6;
    FILL(0, 0);  cp_commit();
    FILL(1, 64); cp_commit();

    int stage = 0, fstage = 2;
    for (int i = 0; i < nk; i++) {
        cp_wait<1>();
        __syncthreads();
        if (i + 2 < nk) {
            FILL(fstage, (i + 2) * 64);
        }
        cp_commit();

        uint32_t Ab = sbase + stage * STAGEB;
        uint32_t Bb = Ab + ASTAGE;

        #pragma unroll
        for (int kk = 0; kk < 4; kk++) {
            uint32_t af[2][4], bfr[4][4];
            #pragma unroll
            for (int mi = 0; mi < 2; mi++)
                ldsm4(af[mi], Ab + (uint32_t)((warpM + mi * 16) * SROW + kk * 32) + aoff);
            #pragma unroll
            for (int p = 0; p < 4; p++)
                ldsm4(bfr[p], Bb + (uint32_t)((warpN + p * 16) * SROW + kk * 32) + boff);
            #pragma unroll
            for (int mi = 0; mi < 2; mi++)
                #pragma unroll
                for (int ni = 0; ni < 8; ni++)
                    mma_bf16(acc[mi][ni], af[mi], &bfr[ni >> 1][(ni & 1) * 2]);
        }

        stage = (stage + 1 == NSTAGE) ? 0 : stage + 1;
        fstage = (fstage + 1 == NSTAGE) ? 0 : fstage + 1;
    }

    // epilogue
    #pragma unroll
    for (int mi = 0; mi < 2; mi++) {
        #pragma unroll
        for (int half = 0; half < 2; half++) {
            int row = bm * 128 + warpM + mi * 16 + r + half * 8;
            int orow = row;
            if (EPI == 2) orow = remap_row(row);
            const float* rr = (EPI == 2 || EPI == 3) ? res + (size_t)orow * N : nullptr;
            #pragma unroll
            for (int ni = 0; ni < 8; ni++) {
                int col = bn * 256 + warpN + ni * 8 + 2 * c;
                float v0 = acc[mi][ni][half * 2 + 0] + bias[col];
                float v1 = acc[mi][ni][half * 2 + 1] + bias[col + 1];
                if (EPI == 1) {
                    v0 = 0.5f * v0 * (1.0f + erff(v0 * 0.70710678118654752f));
                    v1 = 0.5f * v1 * (1.0f + erff(v1 * 0.70710678118654752f));
                }
                if (EPI == 2 || EPI == 3) {
                    v0 += rr[col];
                    v1 += rr[col + 1];
                }
                if (EPI == 0 || EPI == 1) {
                    bf16* cp = (bf16*)Cv + (size_t)orow * N;
                    __nv_bfloat162 pk = {__float2bfloat16(v0), __float2bfloat16(v1)};
                    *(__nv_bfloat162*)(cp + col) = pk;
                } else {
                    float* cp = (float*)Cv + (size_t)orow * N;
                    *(float2*)(cp + col) = make_float2(v0, v1);
                }
            }
        }
    }
#undef FILL
}

// ---------------- tensor-core windowed attention ------------------------------
__global__ void __launch_bounds__(256) attn_tc(const bf16* __restrict__ qkv,
                                               const bf16* __restrict__ comb,
                                               bf16* __restrict__ out) {
    __shared__ __align__(16) bf16 sQ[2][64 * 40];
    __shared__ __align__(16) bf16 sK[2][64 * 40];
    __shared__ __align__(16) bf16 sVT[2][32 * 72];
    __shared__ __align__(16) bf16 sB[2][64 * 72];

    int tid = threadIdx.x;
    int win = blockIdx.x;
    int hg  = blockIdx.y * 2;
    int w64 = win & 63;

    uint32_t* vz = (uint32_t*)sVT;
    for (int i = tid; i < 2 * 32 * 72 / 2; i += 256) vz[i] = 0;
    for (int i = tid; i < 600; i += 256) {
        int h = i / 300, rm = i % 300;
        int row = 49 + rm / 20, w = rm % 20;
        ((uint32_t*)sQ)[h * 1280 + row * 20 + w] = 0;
        ((uint32_t*)sK)[h * 1280 + row * 20 + w] = 0;
    }
    __syncthreads();

    for (int i = tid; i < 392; i += 256) {
        int h = i / 196, rm = i % 196;
        int tok = rm >> 2, ch = rm & 3;
        const bf16* src = qkv + (size_t)(win * 49 + tok) * 768 + (hg + h) * 32 + ch * 8;
        *(uint4*)((char*)sQ + h * 5120 + tok * 80 + ch * 16) = *(const uint4*)src;
        *(uint4*)((char*)sK + h * 5120 + tok * 80 + ch * 16) = *(const uint4*)(src + 256);
    }
    for (int i = tid; i < 1568; i += 256) {
        int h = i / 784, rm = i % 784;
        int tok = rm / 16, dp = (rm % 16) * 2;
        __nv_bfloat162 v = *(const __nv_bfloat162*)(qkv + (size_t)(win * 49 + tok) * 768
                                                    + 512 + (hg + h) * 32 + dp);
        *(bf16*)((char*)sVT + h * 4608 + dp * 144 + tok * 2)       = v.x;
        *(bf16*)((char*)sVT + h * 4608 + (dp + 1) * 144 + tok * 2) = v.y;
    }
    for (int i = tid; i < 1024; i += 256) {
        int h = i >> 9, rm = i & 511;
        int n = rm >> 3, ch = rm & 7;
        const bf16* src = comb + (((size_t)((w64 * 8 + hg + h) * 64 + n)) << 6) + ch * 8;
        *(uint4*)((char*)sB + h * 9216 + n * 144 + ch * 16) = *(const uint4*)src;
    }
    __syncthreads();

    int warp = tid >> 5, lane = tid & 31;
    int head = warp >> 2;
    int rowbase = (warp & 3) * 16;

    uint32_t Qb = smem_u32(sQ) + head * 5120;
    uint32_t Kb = smem_u32(sK) + head * 5120;
    uint32_t Vb = smem_u32(sVT) + head * 4608;
    uint32_t Bb = smem_u32(sB) + head * 9216;

    uint32_t aoff80  = (uint32_t)((lane & 15) * 80 + (lane >> 4) * 16);
    uint32_t aoff144 = (uint32_t)((lane & 15) * 144 + (lane >> 4) * 16);
    uint32_t boff80  = (uint32_t)(((lane & 7) + ((lane >> 4) << 3)) * 80 + ((lane & 8) ? 16 : 0));
    uint32_t boff144 = (uint32_t)(((lane & 7) + ((lane >> 4) << 3)) * 144 + ((lane & 8) ? 16 : 0));

    float sacc[8][4];
    #pragma unroll
    for (int ni = 0; ni < 8; ni++)
        #pragma unroll
        for (int t = 0; t < 4; t++) sacc[ni][t] = 0.0f;

    #pragma unroll
    for (int ks = 0; ks < 2; ks++) {
        uint32_t aq[4], bk[4][4];
        ldsm4(aq, Qb + (uint32_t)(rowbase * 80 + ks * 32) + aoff80);
        #pragma unroll
        for (int p = 0; p < 4; p++)
            ldsm4(bk[p], Kb + (uint32_t)(p * 16 * 80 + ks * 32) + boff80);
        #pragma unroll
        for (int ni = 0; ni < 8; ni++)
            mma_bf16(sacc[ni], aq, &bk[ni >> 1][(ni & 1) * 2]);
    }

    const float scale = 0.17677669529663687f;
    #pragma unroll
    for (int cg = 0; cg < 4; cg++) {
        uint32_t bb[4];
        ldsm4(bb, Bb + (uint32_t)(rowbase * 144 + cg * 32) + aoff144);
        float2 f;
        f = __bfloat1622float2(*(__nv_bfloat162*)&bb[0]);
        sacc[2*cg][0] = sacc[2*cg][0] * scale + f.x;
        sacc[2*cg][1] = sacc[2*cg][1] * scale + f.y;
        f = __bfloat1622float2(*(__nv_bfloat162*)&bb[1]);
        sacc[2*cg][2] = sacc[2*cg][2] * scale + f.x;
        sacc[2*cg][3] = sacc[2*cg][3] * scale + f.y;
        f = __bfloat1622float2(*(__nv_bfloat162*)&bb[2]);
        sacc[2*cg+1][0] = sacc[2*cg+1][0] * scale + f.x;
        sacc[2*cg+1][1] = sacc[2*cg+1][1] * scale + f.y;
        f = __bfloat1622float2(*(__nv_bfloat162*)&bb[3]);
        sacc[2*cg+1][2] = sacc[2*cg+1][2] * scale + f.x;
        sacc[2*cg+1][3] = sacc[2*cg+1][3] * scale + f.y;
    }

    #pragma unroll
    for (int hf = 0; hf < 2; hf++) {
        int i0 = hf * 2;
        float mx = -1e30f;
        #pragma unroll
        for (int ni = 0; ni < 8; ni++)
            mx = fmaxf(mx, fmaxf(sacc[ni][i0], sacc[ni][i0 + 1]));
        mx = fmaxf(mx, __shfl_xor_sync(0xffffffffu, mx, 1));
        mx = fmaxf(mx, __shfl_xor_sync(0xffffffffu, mx, 2));
        float sum = 0.0f;
        #pragma unroll
        for (int ni = 0; ni < 8; ni++) {
            float e0 = expf(sacc[ni][i0] - mx);
            float e1 = expf(sacc[ni][i0 + 1] - mx);
            sacc[ni][i0] = e0; sacc[ni][i0 + 1] = e1;
            sum += e0 + e1;
        }
        sum += __shfl_xor_sync(0xffffffffu, sum, 1);
        sum += __shfl_xor_sync(0xffffffffu, sum, 2);
        float inv = 1.0f / sum;
        #pragma unroll
        for (int ni = 0; ni < 8; ni++) {
            sacc[ni][i0] *= inv; sacc[ni][i0 + 1] *= inv;
        }
    }

    uint32_t pa[4][4];
    #pragma unroll
    for (int ks = 0; ks < 4; ks++) {
        pa[ks][0] = pack_bf16x2(sacc[2*ks][0],   sacc[2*ks][1]);
        pa[ks][1] = pack_bf16x2(sacc[2*ks][2],   sacc[2*ks][3]);
        pa[ks][2] = pack_bf16x2(sacc[2*ks+1][0], sacc[2*ks+1][1]);
        pa[ks][3] = pack_bf16x2(sacc[2*ks+1][2], sacc[2*ks+1][3]);
    }

    float oacc[4][4];
    #pragma unroll
    for (int ni = 0; ni < 4; ni++)
        #pragma unroll
        for (int t = 0; t < 4; t++) oacc[ni][t] = 0.0f;

    #pragma unroll
    for (int ks = 0; ks < 4; ks++) {
        uint32_t bv[2][4];
        #pragma unroll
        for (int p = 0; p < 2; p++)
            ldsm4(bv[p], Vb + (uint32_t)(p * 16 * 144 + ks * 32) + boff144);
        #pragma unroll
        for (int ni = 0; ni < 4; ni++)
            mma_bf16(oacc[ni], pa[ks], &bv[ni >> 1][(ni & 1) * 2]);
    }

    int gh = hg + head;
    int r0 = rowbase + (lane >> 2);
    #pragma unroll
    for (int ni = 0; ni < 4; ni++) {
        int col = gh * 32 + ni * 8 + (lane & 3) * 2;
        if (r0 < NTOK) {
            __nv_bfloat162 pk = {__float2bfloat16(oacc[ni][0]), __float2bfloat16(oacc[ni][1])};
            *(__nv_bfloat162*)(out + (size_t)(win * 49 + r0) * 256 + col) = pk;
        }
        if (r0 + 8 < NTOK) {
            __nv_bfloat162 pk = {__float2bfloat16(oacc[ni][2]), __float2bfloat16(oacc[ni][3])};
            *(__nv_bfloat162*)(out + (size_t)(win * 49 + r0 + 8) * 256 + col) = pk;
        }
    }
}

// ---------------- launcher ---------------------------------------------------
extern "C" void kernel_launch(void* const* d_in, const int* in_sizes, int n_in,
                              void* d_out, int out_size) {
    const float* x     = (const float*)d_in[0];
    const float* n1w   = (const float*)d_in[1];
    const float* n1b   = (const float*)d_in[2];
    const float* qkvw  = (const float*)d_in[3];
    const float* qkvb  = (const float*)d_in[4];
    const float* rpb   = (const float*)d_in[5];
    const float* projw = (const float*)d_in[6];
    const float* projb = (const float*)d_in[7];
    const float* n2w   = (const float*)d_in[8];
    const float* n2b   = (const float*)d_in[9];
    const float* fc1w  = (const float*)d_in[10];
    const float* fc1b  = (const float*)d_in[11];
    const float* fc2w  = (const float*)d_in[12];
    const float* fc2b  = (const float*)d_in[13];
    const int*   relix = (const int*)d_in[14];
    const float* amask = (const float*)d_in[15];
    float* out = (float*)d_out;

    bf16 *hwin, *qkv, *attn, *h2, *wqkv, *wproj, *wfc1, *wfc2, *comb;
    float *x1;
    cudaGetSymbolAddress((void**)&hwin, g_hwin);
    cudaGetSymbolAddress((void**)&qkv,  g_qkv);
    cudaGetSymbolAddress((void**)&attn, g_attn);
    cudaGetSymbolAddress((void**)&x1,   g_x1);
    cudaGetSymbolAddress((void**)&h2,   g_h2);
    cudaGetSymbolAddress((void**)&wqkv, g_wqkv);
    cudaGetSymbolAddress((void**)&wproj, g_wproj);
    cudaGetSymbolAddress((void**)&wfc1, g_wfc1);
    cudaGetSymbolAddress((void**)&wfc2, g_wfc2);
    cudaGetSymbolAddress((void**)&comb, g_comb);

    cudaFuncSetAttribute(bgemm<0>, cudaFuncAttributeMaxDynamicSharedMemorySize, SMEM_DYN);
    cudaFuncSetAttribute(bgemm<1>, cudaFuncAttributeMaxDynamicSharedMemorySize, SMEM_DYN);
    cudaFuncSetAttribute(bgemm<2>, cudaFuncAttributeMaxDynamicSharedMemorySize, SMEM_DYN);
    cudaFuncSetAttribute(bgemm<3>, cudaFuncAttributeMaxDynamicSharedMemorySize, SMEM_DYN);

    cvt4_kernel<<<dim3(DIM * HIDDEN / 4 / 256, 4), 256>>>(
        qkvw, wqkv, 3 * DIM * DIM,
        projw, wproj, DIM * DIM,
        fc1w, wfc1, HIDDEN * DIM,
        fc2w, wfc2, DIM * HIDDEN);
    comb_kernel<<<dim3(64, 8), 256>>>(rpb, relix, amask, comb);

    // 1. LN1 + shift + window-partition (bf16 out)
    ln_kernel<true><<<MTOT / 8, 256>>>(x, n1w, n1b, hwin);
    // 2. QKV GEMM -> bf16
    bgemm<0><<<dim3(3, MTOT / 128), GTHREADS, SMEM_DYN>>>(hwin, wqkv, qkvb, qkv,
                                                          MTOT, 3 * DIM, DIM, nullptr);
    // 3. tensor-core windowed attention
    attn_tc<<<dim3(BZ * NWIN, 4), 256>>>(qkv, comb, attn);
    // 4. proj GEMM + window-reverse scatter + residual -> f32
    bgemm<2><<<dim3(1, MTOT / 128), GTHREADS, SMEM_DYN>>>(attn, wproj, projb, x1,
                                                          MTOT, DIM, DIM, x);
    // 5. LN2 (bf16 out)
    ln_kernel<false><<<MTOT / 8, 256>>>(x1, n2w, n2b, hwin);
    // 6. FC1 + GELU -> bf16
    bgemm<1><<<dim3(4, MTOT / 128), GTHREADS, SMEM_DYN>>>(hwin, wfc1, fc1b, h2,
                                                          MTOT, HIDDEN, DIM, nullptr);
    // 7. FC2 + residual -> out (f32)
    bgemm<3><<<dim3(1, MTOT / 128), GTHREADS, SMEM_DYN>>>(h2, wfc2, fc2b, out,
                                                          MTOT, DIM, HIDDEN, x1);
}

// round 11
// speedup vs baseline: 1.0910x; 1.0910x over previous
#include <cuda_runtime.h>
#include <cuda_bf16.h>
#include <math.h>
#include <stdint.h>

#define BZ 32
#define HH 56
#define WW 56
#define DIM 256
#define HEADS 8
#define WS 7
#define SHIFT 3
#define NTOK 49
#define NWIN 64
#define HEAD_DIM 32
#define HIDDEN 1024
#define MTOT (BZ*HH*WW)    // 100352 rows

typedef __nv_bfloat16 bf16;

// ---------------- scratch ----------------------------------------------------
__device__ bf16  g_hwin[(size_t)MTOT * DIM];
__device__ bf16  g_qkv [(size_t)MTOT * 3 * DIM];
__device__ bf16  g_attn[(size_t)MTOT * DIM];
__device__ float g_x1  [(size_t)MTOT * DIM];
__device__ bf16  g_h2  [(size_t)MTOT * HIDDEN];
__device__ bf16  g_wqkv[3 * DIM * DIM];
__device__ bf16  g_wproj[DIM * DIM];
__device__ bf16  g_wfc1[HIDDEN * DIM];
__device__ bf16  g_wfc2[DIM * HIDDEN];
__device__ bf16  g_comb[64 * 8 * 64 * 64];

__device__ __forceinline__ int remap_row(int m) {
    int b    = m / (NWIN * NTOK);
    int rem  = m - b * (NWIN * NTOK);
    int wimg = rem / NTOK;
    int n    = rem - wimg * NTOK;
    int hh = (wimg >> 3) * WS + n / WS + SHIFT; if (hh >= HH) hh -= HH;
    int ww = (wimg & 7) * WS + n % WS + SHIFT;  if (ww >= WW) ww -= WW;
    return b * (HH * WW) + hh * WW + ww;
}

// ---------------- ptx helpers -------------------------------------------------
__device__ __forceinline__ uint32_t smem_u32(const void* p) {
    return (uint32_t)__cvta_generic_to_shared(p);
}
__device__ __forceinline__ void cp16(uint32_t dst, const void* src) {
    asm volatile("cp.async.cg.shared.global [%0], [%1], 16;\n" :: "r"(dst), "l"(src));
}
__device__ __forceinline__ void cp_commit() { asm volatile("cp.async.commit_group;\n"); }
template<int N> __device__ __forceinline__ void cp_wait() {
    asm volatile("cp.async.wait_group %0;\n" :: "n"(N));
}
__device__ __forceinline__ void ldsm4(uint32_t* r, uint32_t addr) {
    asm volatile("ldmatrix.sync.aligned.m8n8.x4.shared.b16 {%0,%1,%2,%3}, [%4];"
                 : "=r"(r[0]), "=r"(r[1]), "=r"(r[2]), "=r"(r[3]) : "r"(addr));
}
__device__ __forceinline__ void mma_bf16(float* d, const uint32_t* a, const uint32_t* b) {
    asm volatile(
        "mma.sync.aligned.m16n8k16.row.col.f32.bf16.bf16.f32 "
        "{%0,%1,%2,%3}, {%4,%5,%6,%7}, {%8,%9}, {%0,%1,%2,%3};\n"
        : "+f"(d[0]), "+f"(d[1]), "+f"(d[2]), "+f"(d[3])
        : "r"(a[0]), "r"(a[1]), "r"(a[2]), "r"(a[3]), "r"(b[0]), "r"(b[1]));
}
__device__ __forceinline__ uint32_t pack_bf16x2(float a, float b) {
    __nv_bfloat162 h;
    h.x = __float2bfloat16(a); h.y = __float2bfloat16(b);
    return *(uint32_t*)&h;
}

// ---------------- fp32 -> bf16 weight convert (fused, 4 segs) -----------------
__global__ void cvt4_kernel(const float* s0, bf16* d0, int n0,
                            const float* s1, bf16* d1, int n1,
                            const float* s2, bf16* d2, int n2,
                            const float* s3, bf16* d3, int n3) {
    const float* s; bf16* d; int n;
    switch (blockIdx.y) {
        case 0: s = s0; d = d0; n = n0; break;
        case 1: s = s1; d = d1; n = n1; break;
        case 2: s = s2; d = d2; n = n2; break;
        default: s = s3; d = d3; n = n3; break;
    }
    int i = (blockIdx.x * blockDim.x + threadIdx.x) * 4;
    if (i < n) {
        float4 v = *(const float4*)(s + i);
        __nv_bfloat162 p0 = {__float2bfloat16(v.x), __float2bfloat16(v.y)};
        __nv_bfloat162 p1 = {__float2bfloat16(v.z), __float2bfloat16(v.w)};
        *(__nv_bfloat162*)(d + i)     = p0;
        *(__nv_bfloat162*)(d + i + 2) = p1;
    }
}

// ---------------- comb bias precompute ---------------------------------------
__global__ void comb_kernel(const float* __restrict__ rpb,
                            const int* __restrict__ relix,
                            const float* __restrict__ mask,
                            bf16* __restrict__ comb) {
    int w = blockIdx.x, h = blockIdx.y;
    const float* mw = mask + w * (NTOK * NTOK);
    size_t base = ((size_t)(w * 8 + h)) << 12;
    for (int e = threadIdx.x; e < 4096; e += 256) {
        int n = e >> 6, m = e & 63;
        float v = -1e30f;
        if (n < NTOK && m < NTOK)
            v = rpb[relix[n * NTOK + m] * HEADS + h] + mw[n * NTOK + m];
        comb[base + e] = __float2bfloat16(v);
    }
}

// ---------------- LayerNorm (warp per row, bf16 out) -------------------------
template<bool SHIFTMAP>
__global__ void __launch_bounds__(256) ln_kernel(const float* __restrict__ x,
                                                 const float* __restrict__ gw,
                                                 const float* __restrict__ gb,
                                                 bf16* __restrict__ out) {
    int warp = threadIdx.x >> 5, lane = threadIdx.x & 31;
    int m = blockIdx.x * 8 + warp;
    const float* xr;
    if (SHIFTMAP) {
        int r = remap_row(m);
        xr = x + (size_t)r * DIM;
    } else {
        xr = x + (size_t)m * DIM;
    }
    float4 v0 = *(const float4*)(xr + lane * 4);
    float4 v1 = *(const float4*)(xr + 128 + lane * 4);
    float s  = v0.x + v0.y + v0.z + v0.w + v1.x + v1.y + v1.z + v1.w;
    float sq = v0.x*v0.x + v0.y*v0.y + v0.z*v0.z + v0.w*v0.w
             + v1.x*v1.x + v1.y*v1.y + v1.z*v1.z + v1.w*v1.w;
    #pragma unroll
    for (int o = 16; o; o >>= 1) {
        s  += __shfl_xor_sync(0xffffffffu, s,  o);
        sq += __shfl_xor_sync(0xffffffffu, sq, o);
    }
    float mu  = s * (1.0f / DIM);
    float var = sq * (1.0f / DIM) - mu * mu;
    float rs  = rsqrtf(var + 1e-5f);
    float4 w0 = *(const float4*)(gw + lane * 4);
    float4 w1 = *(const float4*)(gw + 128 + lane * 4);
    float4 b0 = *(const float4*)(gb + lane * 4);
    float4 b1 = *(const float4*)(gb + 128 + lane * 4);
    bf16* orow = out + (size_t)m * DIM;
    __nv_bfloat162 p;
    p = {__float2bfloat16((v0.x-mu)*rs*w0.x+b0.x), __float2bfloat16((v0.y-mu)*rs*w0.y+b0.y)};
    *(__nv_bfloat162*)(orow + lane*4)     = p;
    p = {__float2bfloat16((v0.z-mu)*rs*w0.z+b0.z), __float2bfloat16((v0.w-mu)*rs*w0.w+b0.w)};
    *(__nv_bfloat162*)(orow + lane*4 + 2) = p;
    p = {__float2bfloat16((v1.x-mu)*rs*w1.x+b1.x), __float2bfloat16((v1.y-mu)*rs*w1.y+b1.y)};
    *(__nv_bfloat162*)(orow + 128 + lane*4)     = p;
    p = {__float2bfloat16((v1.z-mu)*rs*w1.z+b1.z), __float2bfloat16((v1.w-mu)*rs*w1.w+b1.w)};
    *(__nv_bfloat162*)(orow + 128 + lane*4 + 2) = p;
}

// ============ persistent-B GEMM (K=256): B slice resident in smem =============
// CTA: owns (bn, gy); loads B[bn*256..+256) x 256 once (132KB), then loops
// over bm tiles {gy, gy+GY, ...}. A-ring: 3 stages x 128x64 (18KB each).
// 512 threads, warp grid 4(m)x4(n), warp tile 32x64.
#define PA_SROW 144
#define PA_STAGE (128 * PA_SROW)        // 18432
#define PB_SROW 528
#define PB_OFF (3 * PA_STAGE)           // 55296
#define PSMEM (PB_OFF + 256 * PB_SROW)  // 190464

template<int EPI>
__global__ void __launch_bounds__(512, 1) pgemm(const bf16* __restrict__ A,
                                               const bf16* __restrict__ Bm,
                                               const float* __restrict__ bias,
                                               void* __restrict__ Cv,
                                               int M, int N,
                                               const float* __restrict__ res,
                                               int GY) {
    const int K = 256;
    extern __shared__ __align__(16) char smem[];
    uint32_t sbase = smem_u32(smem);
    int tid = threadIdx.x;
    int warp = tid >> 5, lane = tid & 31;
    int bn = blockIdx.x, gy = blockIdx.y;
    int warpM = (warp & 3) * 32;
    int warpN = (warp >> 2) * 64;
    int r = lane >> 2, c = lane & 3;
    int mt = M >> 7;                       // 784

    uint32_t sB = sbase + PB_OFF;
    // one-time B slice load: 256 rows x 256 cols bf16
    {
        const bf16* Bbase = Bm + (size_t)(bn * 256) * K;
        #pragma unroll
        for (int rpt = 0; rpt < 16; rpt++) {
            int ch = tid + rpt * 512;
            int row = ch >> 5, col = ch & 31;
            cp16(sB + row * PB_SROW + col * 16, Bbase + (size_t)row * K + col * 8);
        }
    }
    cp_commit();

    uint32_t aoff = (uint32_t)((lane & 15) * PA_SROW + (lane >> 4) * 16);
    uint32_t boff = (uint32_t)(((lane & 7) + ((lane >> 4) << 3)) * PB_SROW
                               + ((lane & 8) ? 16 : 0));

    int ntiles = (mt - gy + GY - 1) / GY;
    int nj = ntiles * 4;

#define FILLA(s, j) do { \
    const bf16* Ab = A + (size_t)(gy + ((j) >> 2) * GY) * 128 * K + ((j) & 3) * 64; \
    uint32_t as = sbase + (s) * PA_STAGE; \
    _Pragma("unroll") \
    for (int rpt = 0; rpt < 2; rpt++) { \
        int ch = tid + rpt * 512; \
        int row = ch >> 3, col = ch & 7; \
        cp16(as + row * PA_SROW + col * 16, Ab + (size_t)row * K + col * 8); \
    } \
} while (0)

    FILLA(0, 0);
    cp_commit();
    if (nj > 1) FILLA(1, 1);
    cp_commit();

    for (int t = 0; t < ntiles; t++) {
        int bm = gy + t * GY;
        float acc[2][8][4];
        #pragma unroll
        for (int mi = 0; mi < 2; mi++)
            #pragma unroll
            for (int ni = 0; ni < 8; ni++)
                #pragma unroll
                for (int q = 0; q < 4; q++) acc[mi][ni][q] = 0.0f;

        #pragma unroll
        for (int s4 = 0; s4 < 4; s4++) {
            int j = t * 4 + s4;
            cp_wait<1>();
            __syncthreads();
            if (j + 2 < nj) FILLA((j + 2) % 3, j + 2);
            cp_commit();

            uint32_t As = sbase + (j % 3) * PA_STAGE;
            #pragma unroll
            for (int kk = 0; kk < 4; kk++) {
                int k16 = s4 * 4 + kk;
                uint32_t af[2][4], bfr[4][4];
                #pragma unroll
                for (int mi = 0; mi < 2; mi++)
                    ldsm4(af[mi], As + (uint32_t)((warpM + mi * 16) * PA_SROW + kk * 32) + aoff);
                #pragma unroll
                for (int p = 0; p < 4; p++)
                    ldsm4(bfr[p], sB + (uint32_t)((warpN + p * 16) * PB_SROW + k16 * 32) + boff);
                #pragma unroll
                for (int mi = 0; mi < 2; mi++)
                    #pragma unroll
                    for (int ni = 0; ni < 8; ni++)
                        mma_bf16(acc[mi][ni], af[mi], &bfr[ni >> 1][(ni & 1) * 2]);
            }
        }

        // epilogue for this tile
        #pragma unroll
        for (int mi = 0; mi < 2; mi++) {
            #pragma unroll
            for (int half = 0; half < 2; half++) {
                int row = bm * 128 + warpM + mi * 16 + r + half * 8;
                int orow = row;
                if (EPI == 2) orow = remap_row(row);
                const float* rr = (EPI == 2 || EPI == 3) ? res + (size_t)orow * N : nullptr;
                #pragma unroll
                for (int ni = 0; ni < 8; ni++) {
                    int col = bn * 256 + warpN + ni * 8 + 2 * c;
                    float v0 = acc[mi][ni][half * 2 + 0] + bias[col];
                    float v1 = acc[mi][ni][half * 2 + 1] + bias[col + 1];
                    if (EPI == 1) {
                        v0 = 0.5f * v0 * (1.0f + erff(v0 * 0.70710678118654752f));
                        v1 = 0.5f * v1 * (1.0f + erff(v1 * 0.70710678118654752f));
                    }
                    if (EPI == 2 || EPI == 3) {
                        v0 += rr[col];
                        v1 += rr[col + 1];
                    }
                    if (EPI == 0 || EPI == 1) {
                        bf16* cp = (bf16*)Cv + (size_t)orow * N;
                        __nv_bfloat162 pk = {__float2bfloat16(v0), __float2bfloat16(v1)};
                        *(__nv_bfloat162*)(cp + col) = pk;
                    } else {
                        float* cp = (float*)Cv + (size_t)orow * N;
                        *(float2*)(cp + col) = make_float2(v0, v1);
                    }
                }
            }
        }
    }
#undef FILLA
}

// ---------------- streaming GEMM (for fc2, K=1024) ---------------------------
#define SROW 144
#define ASTAGE (128 * SROW)
#define BSTAGE (256 * SROW)
#define STAGEB (ASTAGE + BSTAGE)
#define NSTAGE 3
#define SMEM_DYN (NSTAGE * STAGEB)  // 165888
#define GTHREADS 512

template<int EPI>
__global__ void __launch_bounds__(GTHREADS, 1) bgemm(const bf16* __restrict__ A,
                                                    const bf16* __restrict__ Bm,
                                                    const float* __restrict__ bias,
                                                    void* __restrict__ Cv,
                                                    int M, int N, int K,
                                                    const float* __restrict__ res) {
    extern __shared__ __align__(16) char smem[];
    uint32_t sbase = smem_u32(smem);
    int tid = threadIdx.x;
    int bn = blockIdx.x, bm = blockIdx.y;
    int warp = tid >> 5, lane = tid & 31;
    int warpM = (warp & 3) * 32;
    int warpN = (warp >> 2) * 64;
    int r = lane >> 2, c = lane & 3;

    int arw[2], acc_[2], brw[4], bcc[4];
    #pragma unroll
    for (int rpt = 0; rpt < 2; rpt++) {
        int ch = tid + rpt * GTHREADS;
        arw[rpt] = ch >> 3; acc_[rpt] = ch & 7;
    }
    #pragma unroll
    for (int rpt = 0; rpt < 4; rpt++) {
        int ch = tid + rpt * GTHREADS;
        brw[rpt] = ch >> 3; bcc[rpt] = ch & 7;
    }
    const bf16* Abase = A  + (size_t)(bm * 128) * K;
    const bf16* Bbase = Bm + (size_t)(bn * 256) * K;

    uint32_t aoff = (uint32_t)((lane & 15) * SROW + (lane >> 4) * 16);
    uint32_t boff = (uint32_t)(((lane & 7) + ((lane >> 4) << 3)) * SROW + ((lane & 8) ? 16 : 0));

    float acc[2][8][4];
    #pragma unroll
    for (int mi = 0; mi < 2; mi++)
        #pragma unroll
        for (int ni = 0; ni < 8; ni++)
            #pragma unroll
            for (int t = 0; t < 4; t++) acc[mi][ni][t] = 0.0f;

#define FILL(s, k0) do { \
    uint32_t ab = sbase + (s) * STAGEB; \
    uint32_t bb = ab + ASTAGE; \
    _Pragma("unroll") \
    for (int rpt = 0; rpt < 2; rpt++) \
        cp16(ab + arw[rpt] * SROW + acc_[rpt] * 16, \
             Abase + (size_t)arw[rpt] * K + (k0) + acc_[rpt] * 8); \
    _Pragma("unroll") \
    for (int rpt = 0; rpt < 4; rpt++) \
        cp16(bb + brw[rpt] * SROW + bcc[rpt] * 16, \
             Bbase + (size_t)brw[rpt] * K + (k0) + bcc[rpt] * 8); \
} while (0)

    int nk = K >> 6;
    FILL(0, 0);  cp_commit();
    FILL(1, 64); cp_commit();

    int stage = 0, fstage = 2;
    for (int i = 0; i < nk; i++) {
        cp_wait<1>();
        __syncthreads();
        if (i + 2 < nk) {
            FILL(fstage, (i + 2) * 64);
        }
        cp_commit();

        uint32_t Ab = sbase + stage * STAGEB;
        uint32_t Bb = Ab + ASTAGE;

        #pragma unroll
        for (int kk = 0; kk < 4; kk++) {
            uint32_t af[2][4], bfr[4][4];
            #pragma unroll
            for (int mi = 0; mi < 2; mi++)
                ldsm4(af[mi], Ab + (uint32_t)((warpM + mi * 16) * SROW + kk * 32) + aoff);
            #pragma unroll
            for (int p = 0; p < 4; p++)
                ldsm4(bfr[p], Bb + (uint32_t)((warpN + p * 16) * SROW + kk * 32) + boff);
            #pragma unroll
            for (int mi = 0; mi < 2; mi++)
                #pragma unroll
                for (int ni = 0; ni < 8; ni++)
                    mma_bf16(acc[mi][ni], af[mi], &bfr[ni >> 1][(ni & 1) * 2]);
        }

        stage = (stage + 1 == NSTAGE) ? 0 : stage + 1;
        fstage = (fstage + 1 == NSTAGE) ? 0 : fstage + 1;
    }

    #pragma unroll
    for (int mi = 0; mi < 2; mi++) {
        #pragma unroll
        for (int half = 0; half < 2; half++) {
            int row = bm * 128 + warpM + mi * 16 + r + half * 8;
            int orow = row;
            if (EPI == 2) orow = remap_row(row);
            const float* rr = (EPI == 2 || EPI == 3) ? res + (size_t)orow * N : nullptr;
            #pragma unroll
            for (int ni = 0; ni < 8; ni++) {
                int col = bn * 256 + warpN + ni * 8 + 2 * c;
                float v0 = acc[mi][ni][half * 2 + 0] + bias[col];
                float v1 = acc[mi][ni][half * 2 + 1] + bias[col + 1];
                if (EPI == 1) {
                    v0 = 0.5f * v0 * (1.0f + erff(v0 * 0.70710678118654752f));
                    v1 = 0.5f * v1 * (1.0f + erff(v1 * 0.70710678118654752f));
                }
                if (EPI == 2 || EPI == 3) {
                    v0 += rr[col];
                    v1 += rr[col + 1];
                }
                if (EPI == 0 || EPI == 1) {
                    bf16* cp = (bf16*)Cv + (size_t)orow * N;
                    __nv_bfloat162 pk = {__float2bfloat16(v0), __float2bfloat16(v1)};
                    *(__nv_bfloat162*)(cp + col) = pk;
                } else {
                    float* cp = (float*)Cv + (size_t)orow * N;
                    *(float2*)(cp + col) = make_float2(v0, v1);
                }
            }
        }
    }
#undef FILL
}

// ---------------- tensor-core windowed attention ------------------------------
__global__ void __launch_bounds__(256) attn_tc(const bf16* __restrict__ qkv,
                                               const bf16* __restrict__ comb,
                                               bf16* __restrict__ out) {
    __shared__ __align__(16) bf16 sQ[2][64 * 40];
    __shared__ __align__(16) bf16 sK[2][64 * 40];
    __shared__ __align__(16) bf16 sVT[2][32 * 72];
    __shared__ __align__(16) bf16 sB[2][64 * 72];

    int tid = threadIdx.x;
    int win = blockIdx.x;
    int hg  = blockIdx.y * 2;
    int w64 = win & 63;

    uint32_t* vz = (uint32_t*)sVT;
    for (int i = tid; i < 2 * 32 * 72 / 2; i += 256) vz[i] = 0;
    for (int i = tid; i < 600; i += 256) {
        int h = i / 300, rm = i % 300;
        int row = 49 + rm / 20, w = rm % 20;
        ((uint32_t*)sQ)[h * 1280 + row * 20 + w] = 0;
        ((uint32_t*)sK)[h * 1280 + row * 20 + w] = 0;
    }
    __syncthreads();

    for (int i = tid; i < 392; i += 256) {
        int h = i / 196, rm = i % 196;
        int tok = rm >> 2, ch = rm & 3;
        const bf16* src = qkv + (size_t)(win * 49 + tok) * 768 + (hg + h) * 32 + ch * 8;
        *(uint4*)((char*)sQ + h * 5120 + tok * 80 + ch * 16) = *(const uint4*)src;
        *(uint4*)((char*)sK + h * 5120 + tok * 80 + ch * 16) = *(const uint4*)(src + 256);
    }
    for (int i = tid; i < 1568; i += 256) {
        int h = i / 784, rm = i % 784;
        int tok = rm / 16, dp = (rm % 16) * 2;
        __nv_bfloat162 v = *(const __nv_bfloat162*)(qkv + (size_t)(win * 49 + tok) * 768
                                                    + 512 + (hg + h) * 32 + dp);
        *(bf16*)((char*)sVT + h * 4608 + dp * 144 + tok * 2)       = v.x;
        *(bf16*)((char*)sVT + h * 4608 + (dp + 1) * 144 + tok * 2) = v.y;
    }
    for (int i = tid; i < 1024; i += 256) {
        int h = i >> 9, rm = i & 511;
        int n = rm >> 3, ch = rm & 7;
        const bf16* src = comb + (((size_t)((w64 * 8 + hg + h) * 64 + n)) << 6) + ch * 8;
        *(uint4*)((char*)sB + h * 9216 + n * 144 + ch * 16) = *(const uint4*)src;
    }
    __syncthreads();

    int warp = tid >> 5, lane = tid & 31;
    int head = warp >> 2;
    int rowbase = (warp & 3) * 16;

    uint32_t Qb = smem_u32(sQ) + head * 5120;
    uint32_t Kb = smem_u32(sK) + head * 5120;
    uint32_t Vb = smem_u32(sVT) + head * 4608;
    uint32_t Bb = smem_u32(sB) + head * 9216;

    uint32_t aoff80  = (uint32_t)((lane & 15) * 80 + (lane >> 4) * 16);
    uint32_t aoff144 = (uint32_t)((lane & 15) * 144 + (lane >> 4) * 16);
    uint32_t boff80  = (uint32_t)(((lane & 7) + ((lane >> 4) << 3)) * 80 + ((lane & 8) ? 16 : 0));
    uint32_t boff144 = (uint32_t)(((lane & 7) + ((lane >> 4) << 3)) * 144 + ((lane & 8) ? 16 : 0));

    float sacc[8][4];
    #pragma unroll
    for (int ni = 0; ni < 8; ni++)
        #pragma unroll
        for (int t = 0; t < 4; t++) sacc[ni][t] = 0.0f;

    #pragma unroll
    for (int ks = 0; ks < 2; ks++) {
        uint32_t aq[4], bk[4][4];
        ldsm4(aq, Qb + (uint32_t)(rowbase * 80 + ks * 32) + aoff80);
        #pragma unroll
        for (int p = 0; p < 4; p++)
            ldsm4(bk[p], Kb + (uint32_t)(p * 16 * 80 + ks * 32) + boff80);
        #pragma unroll
        for (int ni = 0; ni < 8; ni++)
            mma_bf16(sacc[ni], aq, &bk[ni >> 1][(ni & 1) * 2]);
    }

    const float scale = 0.17677669529663687f;
    #pragma unroll
    for (int cg = 0; cg < 4; cg++) {
        uint32_t bb[4];
        ldsm4(bb, Bb + (uint32_t)(rowbase * 144 + cg * 32) + aoff144);
        float2 f;
        f = __bfloat1622float2(*(__nv_bfloat162*)&bb[0]);
        sacc[2*cg][0] = sacc[2*cg][0] * scale + f.x;
        sacc[2*cg][1] = sacc[2*cg][1] * scale + f.y;
        f = __bfloat1622float2(*(__nv_bfloat162*)&bb[1]);
        sacc[2*cg][2] = sacc[2*cg][2] * scale + f.x;
        sacc[2*cg][3] = sacc[2*cg][3] * scale + f.y;
        f = __bfloat1622float2(*(__nv_bfloat162*)&bb[2]);
        sacc[2*cg+1][0] = sacc[2*cg+1][0] * scale + f.x;
        sacc[2*cg+1][1] = sacc[2*cg+1][1] * scale + f.y;
        f = __bfloat1622float2(*(__nv_bfloat162*)&bb[3]);
        sacc[2*cg+1][2] = sacc[2*cg+1][2] * scale + f.x;
        sacc[2*cg+1][3] = sacc[2*cg+1][3] * scale + f.y;
    }

    #pragma unroll
    for (int hf = 0; hf < 2; hf++) {
        int i0 = hf * 2;
        float mx = -1e30f;
        #pragma unroll
        for (int ni = 0; ni < 8; ni++)
            mx = fmaxf(mx, fmaxf(sacc[ni][i0], sacc[ni][i0 + 1]));
        mx = fmaxf(mx, __shfl_xor_sync(0xffffffffu, mx, 1));
        mx = fmaxf(mx, __shfl_xor_sync(0xffffffffu, mx, 2));
        float sum = 0.0f;
        #pragma unroll
        for (int ni = 0; ni < 8; ni++) {
            float e0 = expf(sacc[ni][i0] - mx);
            float e1 = expf(sacc[ni][i0 + 1] - mx);
            sacc[ni][i0] = e0; sacc[ni][i0 + 1] = e1;
            sum += e0 + e1;
        }
        sum += __shfl_xor_sync(0xffffffffu, sum, 1);
        sum += __shfl_xor_sync(0xffffffffu, sum, 2);
        float inv = 1.0f / sum;
        #pragma unroll
        for (int ni = 0; ni < 8; ni++) {
            sacc[ni][i0] *= inv; sacc[ni][i0 + 1] *= inv;
        }
    }

    uint32_t pa[4][4];
    #pragma unroll
    for (int ks = 0; ks < 4; ks++) {
        pa[ks][0] = pack_bf16x2(sacc[2*ks][0],   sacc[2*ks][1]);
        pa[ks][1] = pack_bf16x2(sacc[2*ks][2],   sacc[2*ks][3]);
        pa[ks][2] = pack_bf16x2(sacc[2*ks+1][0], sacc[2*ks+1][1]);
        pa[ks][3] = pack_bf16x2(sacc[2*ks+1][2], sacc[2*ks+1][3]);
    }

    float oacc[4][4];
    #pragma unroll
    for (int ni = 0; ni < 4; ni++)
        #pragma unroll
        for (int t = 0; t < 4; t++) oacc[ni][t] = 0.0f;

    #pragma unroll
    for (int ks = 0; ks < 4; ks++) {
        uint32_t bv[2][4];
        #pragma unroll
        for (int p = 0; p < 2; p++)
            ldsm4(bv[p], Vb + (uint32_t)(p * 16 * 144 + ks * 32) + boff144);
        #pragma unroll
        for (int ni = 0; ni < 4; ni++)
            mma_bf16(oacc[ni], pa[ks], &bv[ni >> 1][(ni & 1) * 2]);
    }

    int gh = hg + head;
    int r0 = rowbase + (lane >> 2);
    #pragma unroll
    for (int ni = 0; ni < 4; ni++) {
        int col = gh * 32 + ni * 8 + (lane & 3) * 2;
        if (r0 < NTOK) {
            __nv_bfloat162 pk = {__float2bfloat16(oacc[ni][0]), __float2bfloat16(oacc[ni][1])};
            *(__nv_bfloat162*)(out + (size_t)(win * 49 + r0) * 256 + col) = pk;
        }
        if (r0 + 8 < NTOK) {
            __nv_bfloat162 pk = {__float2bfloat16(oacc[ni][2]), __float2bfloat16(oacc[ni][3])};
            *(__nv_bfloat162*)(out + (size_t)(win * 49 + r0 + 8) * 256 + col) = pk;
        }
    }
}

// ---------------- launcher ---------------------------------------------------
extern "C" void kernel_launch(void* const* d_in, const int* in_sizes, int n_in,
                              void* d_out, int out_size) {
    const float* x     = (const float*)d_in[0];
    const float* n1w   = (const float*)d_in[1];
    const float* n1b   = (const float*)d_in[2];
    const float* qkvw  = (const float*)d_in[3];
    const float* qkvb  = (const float*)d_in[4];
    const float* rpb   = (const float*)d_in[5];
    const float* projw = (const float*)d_in[6];
    const float* projb = (const float*)d_in[7];
    const float* n2w   = (const float*)d_in[8];
    const float* n2b   = (const float*)d_in[9];
    const float* fc1w  = (const float*)d_in[10];
    const float* fc1b  = (const float*)d_in[11];
    const float* fc2w  = (const float*)d_in[12];
    const float* fc2b  = (const float*)d_in[13];
    const int*   relix = (const int*)d_in[14];
    const float* amask = (const float*)d_in[15];
    float* out = (float*)d_out;

    bf16 *hwin, *qkv, *attn, *h2, *wqkv, *wproj, *wfc1, *wfc2, *comb;
    float *x1;
    cudaGetSymbolAddress((void**)&hwin, g_hwin);
    cudaGetSymbolAddress((void**)&qkv,  g_qkv);
    cudaGetSymbolAddress((void**)&attn, g_attn);
    cudaGetSymbolAddress((void**)&x1,   g_x1);
    cudaGetSymbolAddress((void**)&h2,   g_h2);
    cudaGetSymbolAddress((void**)&wqkv, g_wqkv);
    cudaGetSymbolAddress((void**)&wproj, g_wproj);
    cudaGetSymbolAddress((void**)&wfc1, g_wfc1);
    cudaGetSymbolAddress((void**)&wfc2, g_wfc2);
    cudaGetSymbolAddress((void**)&comb, g_comb);

    cudaFuncSetAttribute(pgemm<0>, cudaFuncAttributeMaxDynamicSharedMemorySize, PSMEM);
    cudaFuncSetAttribute(pgemm<1>, cudaFuncAttributeMaxDynamicSharedMemorySize, PSMEM);
    cudaFuncSetAttribute(pgemm<2>, cudaFuncAttributeMaxDynamicSharedMemorySize, PSMEM);
    cudaFuncSetAttribute(bgemm<3>, cudaFuncAttributeMaxDynamicSharedMemorySize, SMEM_DYN);

    cvt4_kernel<<<dim3(DIM * HIDDEN / 4 / 256, 4), 256>>>(
        qkvw, wqkv, 3 * DIM * DIM,
        projw, wproj, DIM * DIM,
        fc1w, wfc1, HIDDEN * DIM,
        fc2w, wfc2, DIM * HIDDEN);
    comb_kernel<<<dim3(64, 8), 256>>>(rpb, relix, amask, comb);

    // 1. LN1 + shift + window-partition (bf16 out)
    ln_kernel<true><<<MTOT / 8, 256>>>(x, n1w, n1b, hwin);
    // 2. QKV GEMM (persistent-B) -> bf16
    pgemm<0><<<dim3(3, 49), 512, PSMEM>>>(hwin, wqkv, qkvb, qkv, MTOT, 3 * DIM,
                                          nullptr, 49);
    // 3. tensor-core windowed attention
    attn_tc<<<dim3(BZ * NWIN, 4), 256>>>(qkv, comb, attn);
    // 4. proj GEMM (persistent-B) + window-reverse scatter + residual -> f32
    pgemm<2><<<dim3(1, 148), 512, PSMEM>>>(attn, wproj, projb, x1, MTOT, DIM,
                                           x, 148);
    // 5. LN2 (bf16 out)
    ln_kernel<false><<<MTOT / 8, 256>>>(x1, n2w, n2b, hwin);
    // 6. FC1 + GELU (persistent-B) -> bf16
    pgemm<1><<<dim3(4, 37), 512, PSMEM>>>(hwin, wfc1, fc1b, h2, MTOT, HIDDEN,
                                          nullptr, 37);
    // 7. FC2 + residual -> out (f32)  (streaming: K=1024)
    bgemm<3><<<dim3(1, MTOT / 128), GTHREADS, SMEM_DYN>>>(h2, wfc2, fc2b, out,
                                                          MTOT, DIM, HIDDEN, x1);
}